// round 7
// baseline (speedup 1.0000x reference)
#include <cuda_runtime.h>
#include <cuda_bf16.h>

// Problem constants (fixed by the dataset)
#define NN 50000
#define EE 800000
#define ET (EE + NN)   // edges + self loops
#define CC 256         // hidden = out channels
#define F1 128         // input features
#define GG 64          // graphs

// ---------------- scratch (device globals; no allocation allowed) ----------
__device__ float g_H[(size_t)NN * CC];     // h = x @ W (reused both layers)
__device__ float g_X2[(size_t)NN * CC];    // layer-1 output / layer-2 input
__device__ float g_gout[GG * CC];          // graph_emb accumulator (device-local)
__device__ float g_asrc[NN];
__device__ float g_adst[NN];
__device__ float g_alpha[ET];              // per-edge normalized attention
__device__ int   g_off[NN + 1];
__device__ int   g_deg[NN];
__device__ int   g_cur[NN];
__device__ int   g_esrc[ET];

__device__ __forceinline__ int clampN(int v) {
    return v < 0 ? 0 : (v >= NN ? NN - 1 : v);
}

// ---------------- init: deg=1 (self loop), cur=0, zero graph accumulator ----
__global__ void init_kernel() {
    int i = blockIdx.x * blockDim.x + threadIdx.x;
    if (i < NN) { g_deg[i] = 1; g_cur[i] = 0; }
    if (i < GG * CC) g_gout[i] = 0.f;
}

// ---------------- CSR build: count ------------------------------------------
__global__ void count_kernel(const int* __restrict__ ei) {
    int i = blockIdx.x * blockDim.x + threadIdx.x;
    if (i < EE) {
        int d = clampN(ei[EE + i]);   // dst row (edge_index[1])
        atomicAdd(&g_deg[d], 1);
    }
}

// ---------------- CSR build: exclusive scan (single block) ------------------
__global__ void scan_kernel() {
    __shared__ int sums[1024];
    const int t = threadIdx.x;
    const int CH = (NN + 1023) / 1024;   // 49
    int beg = t * CH;
    int end = beg + CH; if (end > NN) end = NN;
    int s = 0;
    for (int i = beg; i < end; i++) s += g_deg[i];
    sums[t] = s;
    __syncthreads();
    for (int d = 1; d < 1024; d <<= 1) {
        int v = 0;
        if (t >= d) v = sums[t - d];
        __syncthreads();
        if (t >= d) sums[t] += v;
        __syncthreads();
    }
    int base = (t == 0) ? 0 : sums[t - 1];
    s = base;
    for (int i = beg; i < end; i++) { s += g_deg[i]; g_off[i + 1] = s; }
    if (t == 0) g_off[0] = 0;
}

// ---------------- CSR build: fill edge sources (incl. self loops) -----------
__global__ void fill_kernel(const int* __restrict__ ei) {
    int i = blockIdx.x * blockDim.x + threadIdx.x;
    if (i < EE) {
        int d = clampN(ei[EE + i]);
        int sv = clampN(ei[i]);
        int p = atomicAdd(&g_cur[d], 1);
        g_esrc[g_off[d] + p] = sv;
    } else if (i < EE + NN) {
        int n = i - EE;
        int p = atomicAdd(&g_cur[n], 1);
        g_esrc[g_off[n] + p] = n;
    }
}

// ================= bf16 split-precision tensor-core GEMM ====================
// C[M,256] = A[M,K] * B[K,256] in ~fp32 precision:
//   A = Ah + Al (bf16 each), B = Bh + Bl;  C += Ah*Bh + Ah*Bl + Al*Bh
// CTA tile 128x128x32, 8 warps of 64x32, mma.sync.m16n8k16.bf16.

__device__ __forceinline__ unsigned pk(__nv_bfloat16 a, __nv_bfloat16 b) {
    return (unsigned)__bfloat16_as_ushort(a) |
           ((unsigned)__bfloat16_as_ushort(b) << 16);
}

__device__ __forceinline__ void ldsm_x4(unsigned& r0, unsigned& r1,
                                        unsigned& r2, unsigned& r3,
                                        unsigned addr) {
    asm volatile("ldmatrix.sync.aligned.m8n8.x4.shared.b16 {%0,%1,%2,%3}, [%4];"
                 : "=r"(r0), "=r"(r1), "=r"(r2), "=r"(r3) : "r"(addr));
}
__device__ __forceinline__ void ldsm_x2t(unsigned& r0, unsigned& r1,
                                         unsigned addr) {
    asm volatile("ldmatrix.sync.aligned.m8n8.x2.trans.shared.b16 {%0,%1}, [%2];"
                 : "=r"(r0), "=r"(r1) : "r"(addr));
}
__device__ __forceinline__ void mma_bf16(float* c, const unsigned* a,
                                         const unsigned* b) {
    asm volatile(
        "mma.sync.aligned.m16n8k16.row.col.f32.bf16.bf16.f32 "
        "{%0,%1,%2,%3}, {%4,%5,%6,%7}, {%8,%9}, {%0,%1,%2,%3};"
        : "+f"(c[0]), "+f"(c[1]), "+f"(c[2]), "+f"(c[3])
        : "r"(a[0]), "r"(a[1]), "r"(a[2]), "r"(a[3]), "r"(b[0]), "r"(b[1]));
}

#define APITCH 40   // bf16 elems per A smem row (32 + 8 pad) -> conflict-free
#define BPITCH 136  // bf16 elems per B smem row (128 + 8 pad)

__global__ __launch_bounds__(256) void mma_gemm_kernel(
    const float* __restrict__ Aext, int use_x2,
    const float* __restrict__ B, int M, int K)
{
    const float* A = use_x2 ? g_X2 : Aext;
    float* C = g_H;

    __shared__ __align__(16) __nv_bfloat16 sAh[128][APITCH];
    __shared__ __align__(16) __nv_bfloat16 sAl[128][APITCH];
    __shared__ __align__(16) __nv_bfloat16 sBh[32][BPITCH];
    __shared__ __align__(16) __nv_bfloat16 sBl[32][BPITCH];

    const int tid  = threadIdx.x;
    const int lane = tid & 31;
    const int wid  = tid >> 5;
    const int wm   = wid & 1;    // 0,1 -> m half (64)
    const int wn   = wid >> 1;   // 0..3 -> n quarter (32)
    const int bm   = blockIdx.x * 128;
    const int bn   = blockIdx.y * 128;

    const int a_m_off = (lane & 7) + ((lane >> 3) & 1) * 8;  // within m16
    const int a_k_off = (lane >> 4) * 8;                     // within k16
    const int b_k_in  = lane & 15;                           // within k16

    const unsigned sAh0 = (unsigned)__cvta_generic_to_shared(&sAh[0][0]);
    const unsigned sAl0 = (unsigned)__cvta_generic_to_shared(&sAl[0][0]);
    const unsigned sBh0 = (unsigned)__cvta_generic_to_shared(&sBh[0][0]);
    const unsigned sBl0 = (unsigned)__cvta_generic_to_shared(&sBl[0][0]);

    float cacc[4][4][4];
#pragma unroll
    for (int i = 0; i < 4; i++)
#pragma unroll
        for (int j = 0; j < 4; j++)
#pragma unroll
            for (int r = 0; r < 4; r++) cacc[i][j][r] = 0.f;

    for (int kt = 0; kt < K; kt += 32) {
        // ---- stage A tile (128 x 32 fp32) as hi/lo bf16 ----
#pragma unroll
        for (int i = 0; i < 4; i++) {
            int idx = tid + i * 256;           // 0..1023
            int row = idx >> 3;                // 0..127
            int c   = (idx & 7) * 4;           // 0..28
            int grow = bm + row;
            float4 v = make_float4(0.f, 0.f, 0.f, 0.f);
            if (grow < M) v = *(const float4*)(A + (size_t)grow * K + kt + c);
            __nv_bfloat16 h0 = __float2bfloat16(v.x);
            __nv_bfloat16 h1 = __float2bfloat16(v.y);
            __nv_bfloat16 h2 = __float2bfloat16(v.z);
            __nv_bfloat16 h3 = __float2bfloat16(v.w);
            __nv_bfloat16 l0 = __float2bfloat16(v.x - __bfloat162float(h0));
            __nv_bfloat16 l1 = __float2bfloat16(v.y - __bfloat162float(h1));
            __nv_bfloat16 l2 = __float2bfloat16(v.z - __bfloat162float(h2));
            __nv_bfloat16 l3 = __float2bfloat16(v.w - __bfloat162float(h3));
            *(uint2*)&sAh[row][c] = make_uint2(pk(h0, h1), pk(h2, h3));
            *(uint2*)&sAl[row][c] = make_uint2(pk(l0, l1), pk(l2, l3));
        }
        // ---- stage B tile (32 x 128 fp32) as hi/lo bf16 ----
#pragma unroll
        for (int i = 0; i < 4; i++) {
            int idx = tid + i * 256;           // 0..1023
            int krow = idx >> 5;               // 0..31
            int c    = (idx & 31) * 4;         // 0..124
            float4 v = *(const float4*)(B + (size_t)(kt + krow) * CC + bn + c);
            __nv_bfloat16 h0 = __float2bfloat16(v.x);
            __nv_bfloat16 h1 = __float2bfloat16(v.y);
            __nv_bfloat16 h2 = __float2bfloat16(v.z);
            __nv_bfloat16 h3 = __float2bfloat16(v.w);
            __nv_bfloat16 l0 = __float2bfloat16(v.x - __bfloat162float(h0));
            __nv_bfloat16 l1 = __float2bfloat16(v.y - __bfloat162float(h1));
            __nv_bfloat16 l2 = __float2bfloat16(v.z - __bfloat162float(h2));
            __nv_bfloat16 l3 = __float2bfloat16(v.w - __bfloat162float(h3));
            *(uint2*)&sBh[krow][c] = make_uint2(pk(h0, h1), pk(h2, h3));
            *(uint2*)&sBl[krow][c] = make_uint2(pk(l0, l1), pk(l2, l3));
        }
        __syncthreads();

        // ---- compute: 2 k16 halves ----
#pragma unroll
        for (int half = 0; half < 2; half++) {
            const int kk = half * 16;
            unsigned ah[4][4], al[4][4], bh[4][2], bl[4][2];
#pragma unroll
            for (int mi = 0; mi < 4; mi++) {
                int m = wm * 64 + mi * 16 + a_m_off;
                unsigned off = (unsigned)(m * APITCH + kk + a_k_off) * 2u;
                ldsm_x4(ah[mi][0], ah[mi][1], ah[mi][2], ah[mi][3], sAh0 + off);
                ldsm_x4(al[mi][0], al[mi][1], al[mi][2], al[mi][3], sAl0 + off);
            }
#pragma unroll
            for (int nj = 0; nj < 4; nj++) {
                int n = wn * 32 + nj * 8;
                unsigned off = (unsigned)((kk + b_k_in) * BPITCH + n) * 2u;
                ldsm_x2t(bh[nj][0], bh[nj][1], sBh0 + off);
                ldsm_x2t(bl[nj][0], bl[nj][1], sBl0 + off);
            }
#pragma unroll
            for (int mi = 0; mi < 4; mi++)
#pragma unroll
                for (int nj = 0; nj < 4; nj++) {
                    mma_bf16(cacc[mi][nj], ah[mi], bh[nj]);
                    mma_bf16(cacc[mi][nj], ah[mi], bl[nj]);
                    mma_bf16(cacc[mi][nj], al[mi], bh[nj]);
                }
        }
        __syncthreads();
    }

    // ---- epilogue: write C (fp32) ----
    const int grp = lane >> 2;          // 0..7 row within m8
    const int qp  = (lane & 3) * 2;     // col pair
#pragma unroll
    for (int mi = 0; mi < 4; mi++) {
        int r0 = bm + wm * 64 + mi * 16 + grp;
#pragma unroll
        for (int nj = 0; nj < 4; nj++) {
            int col = bn + wn * 32 + nj * 8 + qp;
            float* base = C + (size_t)r0 * CC + col;
            if (r0 < M)
                *(float2*)base = make_float2(cacc[mi][nj][0], cacc[mi][nj][1]);
            if (r0 + 8 < M)
                *(float2*)(base + 8 * CC) =
                    make_float2(cacc[mi][nj][2], cacc[mi][nj][3]);
        }
    }
}

// ---------------- per-node attention logit projections -----------------------
__global__ void alpha_kernel(const float* __restrict__ aw_s,
                             const float* __restrict__ aw_d) {
    int w = (blockIdx.x * blockDim.x + threadIdx.x) >> 5;
    if (w >= NN) return;
    int lane = threadIdx.x & 31;
    const float4* hr = (const float4*)(g_H + (size_t)w * CC);
    float s = 0.f, d = 0.f;
#pragma unroll
    for (int j = 0; j < 2; j++) {
        float4 h  = hr[lane * 2 + j];
        float4 a  = ((const float4*)aw_s)[lane * 2 + j];
        float4 dd = ((const float4*)aw_d)[lane * 2 + j];
        s += h.x * a.x + h.y * a.y + h.z * a.z + h.w * a.w;
        d += h.x * dd.x + h.y * dd.y + h.z * dd.z + h.w * dd.w;
    }
#pragma unroll
    for (int o = 16; o > 0; o >>= 1) {
        s += __shfl_xor_sync(0xFFFFFFFFu, s, o);
        d += __shfl_xor_sync(0xFFFFFFFFu, d, o);
    }
    if (lane == 0) { g_asrc[w] = s; g_adst[w] = d; }
}

// ---------------- per-node softmax over incoming edges ----------------------
// One warp per node, lanes strided over its CSR segment.
// Exactly ONE __expf per edge on the chip (vs 64 before).
__global__ void softmax_prep_kernel() {
    int w = (blockIdx.x * blockDim.x + threadIdx.x) >> 5;
    if (w >= NN) return;
    int lane = threadIdx.x & 31;
    int beg = g_off[w], end = g_off[w + 1];
    float ad = g_adst[w];

    float m = -1e30f;
    for (int i = beg + lane; i < end; i += 32) {
        float e = g_asrc[g_esrc[i]] + ad;
        e = e > 0.f ? e : 0.2f * e;           // attention leaky relu
        m = fmaxf(m, e);
    }
#pragma unroll
    for (int o = 16; o > 0; o >>= 1)
        m = fmaxf(m, __shfl_xor_sync(0xFFFFFFFFu, m, o));

    float s = 0.f;
    for (int i = beg + lane; i < end; i += 32) {
        float e = g_asrc[g_esrc[i]] + ad;
        e = e > 0.f ? e : 0.2f * e;
        float p = __expf(e - m);
        g_alpha[i] = p;
        s += p;
    }
#pragma unroll
    for (int o = 16; o > 0; o >>= 1)
        s += __shfl_xor_sync(0xFFFFFFFFu, s, o);
    float inv = 1.f / s;

    for (int i = beg + lane; i < end; i += 32)
        g_alpha[i] *= inv;
}

// ---------------- weighted aggregation (no exp, no serial chain) ------------
// One warp per destination node: lane handles 8 contiguous channels.
template <bool ACT, bool GRAPH>
__global__ void aggregate_kernel(const float* __restrict__ bias,
                                 float* __restrict__ out_ext,
                                 const int* __restrict__ batch) {
    int w = (blockIdx.x * blockDim.x + threadIdx.x) >> 5;
    if (w >= NN) return;
    int lane = threadIdx.x & 31;
    int beg = g_off[w], end = g_off[w + 1];
    float a0 = 0.f, a1 = 0.f, a2 = 0.f, a3 = 0.f;
    float a4 = 0.f, a5 = 0.f, a6 = 0.f, a7 = 0.f;
    float b0 = 0.f, b1v = 0.f, b2v = 0.f, b3 = 0.f;
    float b4 = 0.f, b5 = 0.f, b6 = 0.f, b7 = 0.f;
    const float4* H4 = (const float4*)g_H;

    int i = beg;
    for (; i + 2 <= end; i += 2) {
        int s0 = g_esrc[i];
        int s1 = g_esrc[i + 1];
        float p0 = g_alpha[i];
        float p1 = g_alpha[i + 1];
        float4 v0 = H4[(size_t)s0 * 64 + lane * 2];
        float4 v1 = H4[(size_t)s0 * 64 + lane * 2 + 1];
        float4 u0 = H4[(size_t)s1 * 64 + lane * 2];
        float4 u1 = H4[(size_t)s1 * 64 + lane * 2 + 1];
        a0 = fmaf(p0, v0.x, a0);  a1 = fmaf(p0, v0.y, a1);
        a2 = fmaf(p0, v0.z, a2);  a3 = fmaf(p0, v0.w, a3);
        a4 = fmaf(p0, v1.x, a4);  a5 = fmaf(p0, v1.y, a5);
        a6 = fmaf(p0, v1.z, a6);  a7 = fmaf(p0, v1.w, a7);
        b0 = fmaf(p1, u0.x, b0);  b1v = fmaf(p1, u0.y, b1v);
        b2v = fmaf(p1, u0.z, b2v); b3 = fmaf(p1, u0.w, b3);
        b4 = fmaf(p1, u1.x, b4);  b5 = fmaf(p1, u1.y, b5);
        b6 = fmaf(p1, u1.z, b6);  b7 = fmaf(p1, u1.w, b7);
    }
    if (i < end) {
        int s0 = g_esrc[i];
        float p0 = g_alpha[i];
        float4 v0 = H4[(size_t)s0 * 64 + lane * 2];
        float4 v1 = H4[(size_t)s0 * 64 + lane * 2 + 1];
        a0 = fmaf(p0, v0.x, a0);  a1 = fmaf(p0, v0.y, a1);
        a2 = fmaf(p0, v0.z, a2);  a3 = fmaf(p0, v0.w, a3);
        a4 = fmaf(p0, v1.x, a4);  a5 = fmaf(p0, v1.y, a5);
        a6 = fmaf(p0, v1.z, a6);  a7 = fmaf(p0, v1.w, a7);
    }

    int c = lane * 8;
    float o[8];
    o[0] = a0 + b0  + bias[c + 0];  o[1] = a1 + b1v + bias[c + 1];
    o[2] = a2 + b2v + bias[c + 2];  o[3] = a3 + b3  + bias[c + 3];
    o[4] = a4 + b4  + bias[c + 4];  o[5] = a5 + b5  + bias[c + 5];
    o[6] = a6 + b6  + bias[c + 6];  o[7] = a7 + b7  + bias[c + 7];
    if (ACT) {
#pragma unroll
        for (int j = 0; j < 8; j++) o[j] = o[j] > 0.f ? o[j] : 0.01f * o[j];
    }
    float* out = GRAPH ? out_ext : g_X2;
    float* op = out + (size_t)w * CC + c;
    *(float4*)op       = make_float4(o[0], o[1], o[2], o[3]);
    *(float4*)(op + 4) = make_float4(o[4], o[5], o[6], o[7]);
    if (GRAPH) {
        int g = batch[w];
        g = g < 0 ? 0 : (g >= GG ? GG - 1 : g);
        float* gp = g_gout + g * CC + c;   // device-local accumulator
#pragma unroll
        for (int j = 0; j < 8; j++) atomicAdd(gp + j, o[j]);
    }
}

// ---------------- copy graph accumulator into d_out (plain stores) ----------
__global__ void copy_gout_kernel(float* __restrict__ out) {
    int i = blockIdx.x * blockDim.x + threadIdx.x;
    if (i < GG * CC) out[(size_t)NN * CC + i] = g_gout[i];
}

// ---------------- launch -----------------------------------------------------
extern "C" void kernel_launch(void* const* d_in, const int* in_sizes, int n_in,
                              void* d_out, int out_size) {
    const float* x     = (const float*)d_in[0];
    const int*   ei    = (const int*)d_in[1];     // edge_index: int32 (JAX x64 off)
    const int*   batch = (const int*)d_in[2];     // batch: int32
    const float* W1    = (const float*)d_in[3];
    const float* as1   = (const float*)d_in[4];
    const float* ad1   = (const float*)d_in[5];
    const float* b1    = (const float*)d_in[6];
    const float* W2    = (const float*)d_in[7];
    const float* as2   = (const float*)d_in[8];
    const float* ad2   = (const float*)d_in[9];
    const float* b2    = (const float*)d_in[10];

    float* out = (float*)d_out;

    const int T = 256;
    // CSR build (dst is identical for both layers; built once per launch)
    init_kernel<<<(NN + T - 1) / T, T>>>();
    count_kernel<<<(EE + T - 1) / T, T>>>(ei);
    scan_kernel<<<1, 1024>>>();
    fill_kernel<<<(EE + NN + T - 1) / T, T>>>(ei);

    dim3 ggrid((NN + 127) / 128, CC / 128);
    const int WGRID = (NN * 32 + T - 1) / T;

    // Layer 1
    mma_gemm_kernel<<<ggrid, T>>>(x, 0, W1, NN, F1);
    alpha_kernel<<<WGRID, T>>>(as1, ad1);
    softmax_prep_kernel<<<WGRID, T>>>();
    aggregate_kernel<true, false><<<WGRID, T>>>(b1, nullptr, nullptr);

    // Layer 2
    mma_gemm_kernel<<<ggrid, T>>>(nullptr, 1, W2, NN, CC);
    alpha_kernel<<<WGRID, T>>>(as2, ad2);
    softmax_prep_kernel<<<WGRID, T>>>();
    aggregate_kernel<false, true><<<WGRID, T>>>(b2, out, batch);

    copy_gout_kernel<<<(GG * CC + T - 1) / T, T>>>(out);
}

// round 8
// speedup vs baseline: 1.0090x; 1.0090x over previous
#include <cuda_runtime.h>
#include <cuda_bf16.h>

// Problem constants (fixed by the dataset)
#define NN 50000
#define EE 800000
#define ET (EE + NN)   // edges + self loops
#define CC 256         // hidden = out channels
#define F1 128         // input features
#define GG 64          // graphs
#define SEGCAP 128     // per-warp smem edge buffer

// ---------------- scratch (device globals; no allocation allowed) ----------
__device__ float g_H[(size_t)NN * CC];     // h = x @ W (reused both layers)
__device__ float g_X2[(size_t)NN * CC];    // layer-1 output / layer-2 input
__device__ float g_gout[GG * CC];          // graph_emb accumulator (device-local)
__device__ float g_asrc[NN];
__device__ float g_adst[NN];
__device__ int   g_off[NN + 1];
__device__ int   g_deg[NN];
__device__ int   g_cur[NN];
__device__ int   g_esrc[ET];

__device__ __forceinline__ int clampN(int v) {
    return v < 0 ? 0 : (v >= NN ? NN - 1 : v);
}

// ---------------- init: deg=1 (self loop), cur=0, zero graph accumulator ----
__global__ void init_kernel() {
    int i = blockIdx.x * blockDim.x + threadIdx.x;
    if (i < NN) { g_deg[i] = 1; g_cur[i] = 0; }
    if (i < GG * CC) g_gout[i] = 0.f;
}

// ---------------- CSR build: count ------------------------------------------
__global__ void count_kernel(const int* __restrict__ ei) {
    int i = blockIdx.x * blockDim.x + threadIdx.x;
    if (i < EE) {
        int d = clampN(ei[EE + i]);   // dst row (edge_index[1])
        atomicAdd(&g_deg[d], 1);
    }
}

// ---------------- CSR build: exclusive scan (single block) ------------------
__global__ void scan_kernel() {
    __shared__ int sums[1024];
    const int t = threadIdx.x;
    const int CH = (NN + 1023) / 1024;   // 49
    int beg = t * CH;
    int end = beg + CH; if (end > NN) end = NN;
    int s = 0;
    for (int i = beg; i < end; i++) s += g_deg[i];
    sums[t] = s;
    __syncthreads();
    for (int d = 1; d < 1024; d <<= 1) {
        int v = 0;
        if (t >= d) v = sums[t - d];
        __syncthreads();
        if (t >= d) sums[t] += v;
        __syncthreads();
    }
    int base = (t == 0) ? 0 : sums[t - 1];
    s = base;
    for (int i = beg; i < end; i++) { s += g_deg[i]; g_off[i + 1] = s; }
    if (t == 0) g_off[0] = 0;
}

// ---------------- CSR build: fill edge sources (incl. self loops) -----------
__global__ void fill_kernel(const int* __restrict__ ei) {
    int i = blockIdx.x * blockDim.x + threadIdx.x;
    if (i < EE) {
        int d = clampN(ei[EE + i]);
        int sv = clampN(ei[i]);
        int p = atomicAdd(&g_cur[d], 1);
        g_esrc[g_off[d] + p] = sv;
    } else if (i < EE + NN) {
        int n = i - EE;
        int p = atomicAdd(&g_cur[n], 1);
        g_esrc[g_off[n] + p] = n;
    }
}

// ================= bf16 split-precision tensor-core GEMM ====================
__device__ __forceinline__ unsigned pk(__nv_bfloat16 a, __nv_bfloat16 b) {
    return (unsigned)__bfloat16_as_ushort(a) |
           ((unsigned)__bfloat16_as_ushort(b) << 16);
}

__device__ __forceinline__ void ldsm_x4(unsigned& r0, unsigned& r1,
                                        unsigned& r2, unsigned& r3,
                                        unsigned addr) {
    asm volatile("ldmatrix.sync.aligned.m8n8.x4.shared.b16 {%0,%1,%2,%3}, [%4];"
                 : "=r"(r0), "=r"(r1), "=r"(r2), "=r"(r3) : "r"(addr));
}
__device__ __forceinline__ void ldsm_x2t(unsigned& r0, unsigned& r1,
                                         unsigned addr) {
    asm volatile("ldmatrix.sync.aligned.m8n8.x2.trans.shared.b16 {%0,%1}, [%2];"
                 : "=r"(r0), "=r"(r1) : "r"(addr));
}
__device__ __forceinline__ void mma_bf16(float* c, const unsigned* a,
                                         const unsigned* b) {
    asm volatile(
        "mma.sync.aligned.m16n8k16.row.col.f32.bf16.bf16.f32 "
        "{%0,%1,%2,%3}, {%4,%5,%6,%7}, {%8,%9}, {%0,%1,%2,%3};"
        : "+f"(c[0]), "+f"(c[1]), "+f"(c[2]), "+f"(c[3])
        : "r"(a[0]), "r"(a[1]), "r"(a[2]), "r"(a[3]), "r"(b[0]), "r"(b[1]));
}

#define APITCH 40   // bf16 elems per A smem row (32 + 8 pad) -> conflict-free
#define BPITCH 136  // bf16 elems per B smem row (128 + 8 pad)

__global__ __launch_bounds__(256) void mma_gemm_kernel(
    const float* __restrict__ Aext, int use_x2,
    const float* __restrict__ B, int M, int K)
{
    const float* A = use_x2 ? g_X2 : Aext;
    float* C = g_H;

    __shared__ __align__(16) __nv_bfloat16 sAh[128][APITCH];
    __shared__ __align__(16) __nv_bfloat16 sAl[128][APITCH];
    __shared__ __align__(16) __nv_bfloat16 sBh[32][BPITCH];
    __shared__ __align__(16) __nv_bfloat16 sBl[32][BPITCH];

    const int tid  = threadIdx.x;
    const int lane = tid & 31;
    const int wid  = tid >> 5;
    const int wm   = wid & 1;
    const int wn   = wid >> 1;
    const int bm   = blockIdx.x * 128;
    const int bn   = blockIdx.y * 128;

    const int a_m_off = (lane & 7) + ((lane >> 3) & 1) * 8;
    const int a_k_off = (lane >> 4) * 8;
    const int b_k_in  = lane & 15;

    const unsigned sAh0 = (unsigned)__cvta_generic_to_shared(&sAh[0][0]);
    const unsigned sAl0 = (unsigned)__cvta_generic_to_shared(&sAl[0][0]);
    const unsigned sBh0 = (unsigned)__cvta_generic_to_shared(&sBh[0][0]);
    const unsigned sBl0 = (unsigned)__cvta_generic_to_shared(&sBl[0][0]);

    float cacc[4][4][4];
#pragma unroll
    for (int i = 0; i < 4; i++)
#pragma unroll
        for (int j = 0; j < 4; j++)
#pragma unroll
            for (int r = 0; r < 4; r++) cacc[i][j][r] = 0.f;

    for (int kt = 0; kt < K; kt += 32) {
#pragma unroll
        for (int i = 0; i < 4; i++) {
            int idx = tid + i * 256;
            int row = idx >> 3;
            int c   = (idx & 7) * 4;
            int grow = bm + row;
            float4 v = make_float4(0.f, 0.f, 0.f, 0.f);
            if (grow < M) v = *(const float4*)(A + (size_t)grow * K + kt + c);
            __nv_bfloat16 h0 = __float2bfloat16(v.x);
            __nv_bfloat16 h1 = __float2bfloat16(v.y);
            __nv_bfloat16 h2 = __float2bfloat16(v.z);
            __nv_bfloat16 h3 = __float2bfloat16(v.w);
            __nv_bfloat16 l0 = __float2bfloat16(v.x - __bfloat162float(h0));
            __nv_bfloat16 l1 = __float2bfloat16(v.y - __bfloat162float(h1));
            __nv_bfloat16 l2 = __float2bfloat16(v.z - __bfloat162float(h2));
            __nv_bfloat16 l3 = __float2bfloat16(v.w - __bfloat162float(h3));
            *(uint2*)&sAh[row][c] = make_uint2(pk(h0, h1), pk(h2, h3));
            *(uint2*)&sAl[row][c] = make_uint2(pk(l0, l1), pk(l2, l3));
        }
#pragma unroll
        for (int i = 0; i < 4; i++) {
            int idx = tid + i * 256;
            int krow = idx >> 5;
            int c    = (idx & 31) * 4;
            float4 v = *(const float4*)(B + (size_t)(kt + krow) * CC + bn + c);
            __nv_bfloat16 h0 = __float2bfloat16(v.x);
            __nv_bfloat16 h1 = __float2bfloat16(v.y);
            __nv_bfloat16 h2 = __float2bfloat16(v.z);
            __nv_bfloat16 h3 = __float2bfloat16(v.w);
            __nv_bfloat16 l0 = __float2bfloat16(v.x - __bfloat162float(h0));
            __nv_bfloat16 l1 = __float2bfloat16(v.y - __bfloat162float(h1));
            __nv_bfloat16 l2 = __float2bfloat16(v.z - __bfloat162float(h2));
            __nv_bfloat16 l3 = __float2bfloat16(v.w - __bfloat162float(h3));
            *(uint2*)&sBh[krow][c] = make_uint2(pk(h0, h1), pk(h2, h3));
            *(uint2*)&sBl[krow][c] = make_uint2(pk(l0, l1), pk(l2, l3));
        }
        __syncthreads();

#pragma unroll
        for (int half = 0; half < 2; half++) {
            const int kk = half * 16;
            unsigned ah[4][4], al[4][4], bh[4][2], bl[4][2];
#pragma unroll
            for (int mi = 0; mi < 4; mi++) {
                int m = wm * 64 + mi * 16 + a_m_off;
                unsigned off = (unsigned)(m * APITCH + kk + a_k_off) * 2u;
                ldsm_x4(ah[mi][0], ah[mi][1], ah[mi][2], ah[mi][3], sAh0 + off);
                ldsm_x4(al[mi][0], al[mi][1], al[mi][2], al[mi][3], sAl0 + off);
            }
#pragma unroll
            for (int nj = 0; nj < 4; nj++) {
                int n = wn * 32 + nj * 8;
                unsigned off = (unsigned)((kk + b_k_in) * BPITCH + n) * 2u;
                ldsm_x2t(bh[nj][0], bh[nj][1], sBh0 + off);
                ldsm_x2t(bl[nj][0], bl[nj][1], sBl0 + off);
            }
#pragma unroll
            for (int mi = 0; mi < 4; mi++)
#pragma unroll
                for (int nj = 0; nj < 4; nj++) {
                    mma_bf16(cacc[mi][nj], ah[mi], bh[nj]);
                    mma_bf16(cacc[mi][nj], ah[mi], bl[nj]);
                    mma_bf16(cacc[mi][nj], al[mi], bh[nj]);
                }
        }
        __syncthreads();
    }

    const int grp = lane >> 2;
    const int qp  = (lane & 3) * 2;
#pragma unroll
    for (int mi = 0; mi < 4; mi++) {
        int r0 = bm + wm * 64 + mi * 16 + grp;
#pragma unroll
        for (int nj = 0; nj < 4; nj++) {
            int col = bn + wn * 32 + nj * 8 + qp;
            float* base = C + (size_t)r0 * CC + col;
            if (r0 < M)
                *(float2*)base = make_float2(cacc[mi][nj][0], cacc[mi][nj][1]);
            if (r0 + 8 < M)
                *(float2*)(base + 8 * CC) =
                    make_float2(cacc[mi][nj][2], cacc[mi][nj][3]);
        }
    }
}

// ---------------- per-node attention logit projections -----------------------
__global__ void alpha_kernel(const float* __restrict__ aw_s,
                             const float* __restrict__ aw_d) {
    int w = (blockIdx.x * blockDim.x + threadIdx.x) >> 5;
    if (w >= NN) return;
    int lane = threadIdx.x & 31;
    const float4* hr = (const float4*)(g_H + (size_t)w * CC);
    float s = 0.f, d = 0.f;
#pragma unroll
    for (int j = 0; j < 2; j++) {
        float4 h  = hr[lane * 2 + j];
        float4 a  = ((const float4*)aw_s)[lane * 2 + j];
        float4 dd = ((const float4*)aw_d)[lane * 2 + j];
        s += h.x * a.x + h.y * a.y + h.z * a.z + h.w * a.w;
        d += h.x * dd.x + h.y * dd.y + h.z * dd.z + h.w * dd.w;
    }
#pragma unroll
    for (int o = 16; o > 0; o >>= 1) {
        s += __shfl_xor_sync(0xFFFFFFFFu, s, o);
        d += __shfl_xor_sync(0xFFFFFFFFu, d, o);
    }
    if (lane == 0) { g_asrc[w] = s; g_adst[w] = d; }
}

// ---------------- fused softmax + aggregation (warp per node) ----------------
// Pass 1: stage idx+logits in smem, warp-max. Pass 2: exp, warp-sum.
// Pass B: sequential smem sweep, independent-FMA gather accumulation.
template <bool ACT, bool GRAPH>
__global__ __launch_bounds__(256) void aggregate_kernel(
    const float* __restrict__ bias,
    float* __restrict__ out_ext,
    const int* __restrict__ batch) {
    __shared__ int   s_idx[8][SEGCAP];
    __shared__ float s_p[8][SEGCAP];

    int w = (blockIdx.x * blockDim.x + threadIdx.x) >> 5;
    if (w >= NN) return;
    int lane = threadIdx.x & 31;
    int wl   = (threadIdx.x >> 5) & 7;
    int beg = g_off[w], end = g_off[w + 1];
    int deg = end - beg;
    float ad = g_adst[w];

    float a0 = 0.f, a1 = 0.f, a2 = 0.f, a3 = 0.f;
    float a4 = 0.f, a5 = 0.f, a6 = 0.f, a7 = 0.f;
    float b0 = 0.f, b1v = 0.f, b2v = 0.f, b3 = 0.f;
    float b4 = 0.f, b5 = 0.f, b6 = 0.f, b7 = 0.f;
    const float4* H4 = (const float4*)g_H;
    float ssum = 0.f;

    if (deg <= SEGCAP) {
        // ---- pass 1: stage indices + logits, find max ----
        float m = -1e30f;
        for (int j = lane; j < deg; j += 32) {
            int src = g_esrc[beg + j];
            s_idx[wl][j] = src;
            float e = g_asrc[src] + ad;
            e = e > 0.f ? e : 0.2f * e;
            s_p[wl][j] = e;
            m = fmaxf(m, e);
        }
#pragma unroll
        for (int o = 16; o > 0; o >>= 1)
            m = fmaxf(m, __shfl_xor_sync(0xFFFFFFFFu, m, o));
        __syncwarp();
        // ---- pass 2: exponentiate (1 exp per edge chip-wide), sum ----
        for (int j = lane; j < deg; j += 32) {
            float p = __expf(s_p[wl][j] - m);
            s_p[wl][j] = p;
            ssum += p;
        }
#pragma unroll
        for (int o = 16; o > 0; o >>= 1)
            ssum += __shfl_xor_sync(0xFFFFFFFFu, ssum, o);
        __syncwarp();
        // ---- pass B: gather + independent FMAs, 2-way unrolled ----
        int j = 0;
        for (; j + 2 <= deg; j += 2) {
            int s0 = s_idx[wl][j];
            int s1 = s_idx[wl][j + 1];
            float p0 = s_p[wl][j];
            float p1 = s_p[wl][j + 1];
            float4 v0 = H4[(size_t)s0 * 64 + lane * 2];
            float4 v1 = H4[(size_t)s0 * 64 + lane * 2 + 1];
            float4 u0 = H4[(size_t)s1 * 64 + lane * 2];
            float4 u1 = H4[(size_t)s1 * 64 + lane * 2 + 1];
            a0 = fmaf(p0, v0.x, a0);  a1 = fmaf(p0, v0.y, a1);
            a2 = fmaf(p0, v0.z, a2);  a3 = fmaf(p0, v0.w, a3);
            a4 = fmaf(p0, v1.x, a4);  a5 = fmaf(p0, v1.y, a5);
            a6 = fmaf(p0, v1.z, a6);  a7 = fmaf(p0, v1.w, a7);
            b0 = fmaf(p1, u0.x, b0);  b1v = fmaf(p1, u0.y, b1v);
            b2v = fmaf(p1, u0.z, b2v); b3 = fmaf(p1, u0.w, b3);
            b4 = fmaf(p1, u1.x, b4);  b5 = fmaf(p1, u1.y, b5);
            b6 = fmaf(p1, u1.z, b6);  b7 = fmaf(p1, u1.w, b7);
        }
        if (j < deg) {
            int s0 = s_idx[wl][j];
            float p0 = s_p[wl][j];
            float4 v0 = H4[(size_t)s0 * 64 + lane * 2];
            float4 v1 = H4[(size_t)s0 * 64 + lane * 2 + 1];
            a0 = fmaf(p0, v0.x, a0);  a1 = fmaf(p0, v0.y, a1);
            a2 = fmaf(p0, v0.z, a2);  a3 = fmaf(p0, v0.w, a3);
            a4 = fmaf(p0, v1.x, a4);  a5 = fmaf(p0, v1.y, a5);
            a6 = fmaf(p0, v1.z, a6);  a7 = fmaf(p0, v1.w, a7);
        }
    } else {
        // ---- fallback for deg > SEGCAP (not expected on this dataset) ----
        float m = -1e30f;
        for (int i = beg + lane; i < end; i += 32) {
            float e = g_asrc[g_esrc[i]] + ad;
            e = e > 0.f ? e : 0.2f * e;
            m = fmaxf(m, e);
        }
#pragma unroll
        for (int o = 16; o > 0; o >>= 1)
            m = fmaxf(m, __shfl_xor_sync(0xFFFFFFFFu, m, o));
        for (int i = beg; i < end; i++) {
            int src = g_esrc[i];
            float e = g_asrc[src] + ad;
            e = e > 0.f ? e : 0.2f * e;
            float p = __expf(e - m);
            if (lane == 0) ssum += p;
            float4 v0 = H4[(size_t)src * 64 + lane * 2];
            float4 v1 = H4[(size_t)src * 64 + lane * 2 + 1];
            a0 = fmaf(p, v0.x, a0);  a1 = fmaf(p, v0.y, a1);
            a2 = fmaf(p, v0.z, a2);  a3 = fmaf(p, v0.w, a3);
            a4 = fmaf(p, v1.x, a4);  a5 = fmaf(p, v1.y, a5);
            a6 = fmaf(p, v1.z, a6);  a7 = fmaf(p, v1.w, a7);
        }
        ssum = __shfl_sync(0xFFFFFFFFu, ssum, 0);
    }

    float inv = 1.f / ssum;
    int c = lane * 8;
    float o[8];
    o[0] = (a0 + b0)  * inv + bias[c + 0];
    o[1] = (a1 + b1v) * inv + bias[c + 1];
    o[2] = (a2 + b2v) * inv + bias[c + 2];
    o[3] = (a3 + b3)  * inv + bias[c + 3];
    o[4] = (a4 + b4)  * inv + bias[c + 4];
    o[5] = (a5 + b5)  * inv + bias[c + 5];
    o[6] = (a6 + b6)  * inv + bias[c + 6];
    o[7] = (a7 + b7)  * inv + bias[c + 7];
    if (ACT) {
#pragma unroll
        for (int j = 0; j < 8; j++) o[j] = o[j] > 0.f ? o[j] : 0.01f * o[j];
    }
    float* out = GRAPH ? out_ext : g_X2;
    float* op = out + (size_t)w * CC + c;
    *(float4*)op       = make_float4(o[0], o[1], o[2], o[3]);
    *(float4*)(op + 4) = make_float4(o[4], o[5], o[6], o[7]);
    if (GRAPH) {
        int g = batch[w];
        g = g < 0 ? 0 : (g >= GG ? GG - 1 : g);
        float* gp = g_gout + g * CC + c;
#pragma unroll
        for (int j = 0; j < 8; j++) atomicAdd(gp + j, o[j]);
    }
}

// ---------------- copy graph accumulator into d_out (plain stores) ----------
__global__ void copy_gout_kernel(float* __restrict__ out) {
    int i = blockIdx.x * blockDim.x + threadIdx.x;
    if (i < GG * CC) out[(size_t)NN * CC + i] = g_gout[i];
}

// ---------------- launch -----------------------------------------------------
extern "C" void kernel_launch(void* const* d_in, const int* in_sizes, int n_in,
                              void* d_out, int out_size) {
    const float* x     = (const float*)d_in[0];
    const int*   ei    = (const int*)d_in[1];
    const int*   batch = (const int*)d_in[2];
    const float* W1    = (const float*)d_in[3];
    const float* as1   = (const float*)d_in[4];
    const float* ad1   = (const float*)d_in[5];
    const float* b1    = (const float*)d_in[6];
    const float* W2    = (const float*)d_in[7];
    const float* as2   = (const float*)d_in[8];
    const float* ad2   = (const float*)d_in[9];
    const float* b2    = (const float*)d_in[10];

    float* out = (float*)d_out;

    const int T = 256;
    init_kernel<<<(NN + T - 1) / T, T>>>();
    count_kernel<<<(EE + T - 1) / T, T>>>(ei);
    scan_kernel<<<1, 1024>>>();
    fill_kernel<<<(EE + NN + T - 1) / T, T>>>(ei);

    dim3 ggrid((NN + 127) / 128, CC / 128);
    const int WGRID = (NN * 32 + T - 1) / T;

    // Layer 1
    mma_gemm_kernel<<<ggrid, T>>>(x, 0, W1, NN, F1);
    alpha_kernel<<<WGRID, T>>>(as1, ad1);
    aggregate_kernel<true, false><<<WGRID, T>>>(b1, nullptr, nullptr);

    // Layer 2
    mma_gemm_kernel<<<ggrid, T>>>(nullptr, 1, W2, NN, CC);
    alpha_kernel<<<WGRID, T>>>(as2, ad2);
    aggregate_kernel<false, true><<<WGRID, T>>>(b2, out, batch);

    copy_gout_kernel<<<(GG * CC + T - 1) / T, T>>>(out);
}

// round 9
// speedup vs baseline: 1.0993x; 1.0895x over previous
#include <cuda_runtime.h>
#include <cuda_bf16.h>

// Problem constants (fixed by the dataset)
#define NN 50000
#define EE 800000
#define ET (EE + NN)   // edges + self loops
#define CC 256         // hidden = out channels
#define F1 128         // input features
#define GG 64          // graphs

// ---------------- scratch (device globals; no allocation allowed) ----------
__device__ float g_H[(size_t)NN * CC];     // h = x @ W (reused both layers)
__device__ float g_X2[(size_t)NN * CC];    // layer-1 output / layer-2 input
__device__ float g_gout[GG * CC];          // graph_emb accumulator (device-local)
__device__ float g_asrc[NN];
__device__ float g_adst[NN];
__device__ int   g_off[NN + 1];
__device__ int   g_deg[NN];
__device__ int   g_cur[NN];
__device__ int   g_esrc[ET];
__device__ __nv_bfloat16 g_Wh[2 * CC * CC];  // preconverted weights (hi)
__device__ __nv_bfloat16 g_Wl[2 * CC * CC];  // preconverted weights (lo)

__device__ __forceinline__ int clampN(int v) {
    return v < 0 ? 0 : (v >= NN ? NN - 1 : v);
}

// ---------------- pre-convert W1/W2 to bf16 hi/lo ---------------------------
__global__ void cvtW_kernel(const float* __restrict__ W1,
                            const float* __restrict__ W2) {
    int i = blockIdx.x * blockDim.x + threadIdx.x;
    float v; int dst;
    if (i < F1 * CC) { v = W1[i]; dst = i; }
    else if (i < F1 * CC + CC * CC) { v = W2[i - F1 * CC]; dst = CC * CC + (i - F1 * CC); }
    else return;
    __nv_bfloat16 h = __float2bfloat16(v);
    __nv_bfloat16 l = __float2bfloat16(v - __bfloat162float(h));
    g_Wh[dst] = h;
    g_Wl[dst] = l;
}

// ---------------- init: deg=1 (self loop), cur=0, zero graph accumulator ----
__global__ void init_kernel() {
    int i = blockIdx.x * blockDim.x + threadIdx.x;
    if (i < NN) { g_deg[i] = 1; g_cur[i] = 0; }
    if (i < GG * CC) g_gout[i] = 0.f;
}

// ---------------- CSR build: count ------------------------------------------
__global__ void count_kernel(const int* __restrict__ ei) {
    int i = blockIdx.x * blockDim.x + threadIdx.x;
    if (i < EE) {
        int d = clampN(ei[EE + i]);   // dst row (edge_index[1])
        atomicAdd(&g_deg[d], 1);
    }
}

// ---------------- CSR build: exclusive scan (single block) ------------------
__global__ void scan_kernel() {
    __shared__ int sums[1024];
    const int t = threadIdx.x;
    const int CH = (NN + 1023) / 1024;   // 49
    int beg = t * CH;
    int end = beg + CH; if (end > NN) end = NN;
    int s = 0;
    for (int i = beg; i < end; i++) s += g_deg[i];
    sums[t] = s;
    __syncthreads();
    for (int d = 1; d < 1024; d <<= 1) {
        int v = 0;
        if (t >= d) v = sums[t - d];
        __syncthreads();
        if (t >= d) sums[t] += v;
        __syncthreads();
    }
    int base = (t == 0) ? 0 : sums[t - 1];
    s = base;
    for (int i = beg; i < end; i++) { s += g_deg[i]; g_off[i + 1] = s; }
    if (t == 0) g_off[0] = 0;
}

// ---------------- CSR build: fill edge sources (incl. self loops) -----------
__global__ void fill_kernel(const int* __restrict__ ei) {
    int i = blockIdx.x * blockDim.x + threadIdx.x;
    if (i < EE) {
        int d = clampN(ei[EE + i]);
        int sv = clampN(ei[i]);
        int p = atomicAdd(&g_cur[d], 1);
        g_esrc[g_off[d] + p] = sv;
    } else if (i < EE + NN) {
        int n = i - EE;
        int p = atomicAdd(&g_cur[n], 1);
        g_esrc[g_off[n] + p] = n;
    }
}

// ================= bf16 split-precision tensor-core GEMM ====================
__device__ __forceinline__ unsigned pk(__nv_bfloat16 a, __nv_bfloat16 b) {
    return (unsigned)__bfloat16_as_ushort(a) |
           ((unsigned)__bfloat16_as_ushort(b) << 16);
}

__device__ __forceinline__ void ldsm_x4(unsigned& r0, unsigned& r1,
                                        unsigned& r2, unsigned& r3,
                                        unsigned addr) {
    asm volatile("ldmatrix.sync.aligned.m8n8.x4.shared.b16 {%0,%1,%2,%3}, [%4];"
                 : "=r"(r0), "=r"(r1), "=r"(r2), "=r"(r3) : "r"(addr));
}
__device__ __forceinline__ void ldsm_x2t(unsigned& r0, unsigned& r1,
                                         unsigned addr) {
    asm volatile("ldmatrix.sync.aligned.m8n8.x2.trans.shared.b16 {%0,%1}, [%2];"
                 : "=r"(r0), "=r"(r1) : "r"(addr));
}
__device__ __forceinline__ void mma_bf16(float* c, const unsigned* a,
                                         const unsigned* b) {
    asm volatile(
        "mma.sync.aligned.m16n8k16.row.col.f32.bf16.bf16.f32 "
        "{%0,%1,%2,%3}, {%4,%5,%6,%7}, {%8,%9}, {%0,%1,%2,%3};"
        : "+f"(c[0]), "+f"(c[1]), "+f"(c[2]), "+f"(c[3])
        : "r"(a[0]), "r"(a[1]), "r"(a[2]), "r"(a[3]), "r"(b[0]), "r"(b[1]));
}

#define APITCH 40   // bf16 elems per A smem row (32 + 8 pad) -> conflict-free
#define BPITCH 136  // bf16 elems per B smem row (128 + 8 pad)

__global__ __launch_bounds__(256) void mma_gemm_kernel(
    const float* __restrict__ Aext, int use_x2, int lay, int M, int K)
{
    const float* A = use_x2 ? g_X2 : Aext;
    float* C = g_H;

    __shared__ __align__(16) __nv_bfloat16 sAh[128][APITCH];
    __shared__ __align__(16) __nv_bfloat16 sAl[128][APITCH];
    __shared__ __align__(16) __nv_bfloat16 sBh[32][BPITCH];
    __shared__ __align__(16) __nv_bfloat16 sBl[32][BPITCH];

    const int tid  = threadIdx.x;
    const int lane = tid & 31;
    const int wid  = tid >> 5;
    const int wm   = wid & 1;
    const int wn   = wid >> 1;
    const int bm   = blockIdx.x * 128;
    const int bn   = blockIdx.y * 128;

    const int a_m_off = (lane & 7) + ((lane >> 3) & 1) * 8;
    const int a_k_off = (lane >> 4) * 8;
    const int b_k_in  = lane & 15;

    const __nv_bfloat16* Wh = g_Wh + (size_t)lay * CC * CC;
    const __nv_bfloat16* Wl = g_Wl + (size_t)lay * CC * CC;

    const unsigned sAh0 = (unsigned)__cvta_generic_to_shared(&sAh[0][0]);
    const unsigned sAl0 = (unsigned)__cvta_generic_to_shared(&sAl[0][0]);
    const unsigned sBh0 = (unsigned)__cvta_generic_to_shared(&sBh[0][0]);
    const unsigned sBl0 = (unsigned)__cvta_generic_to_shared(&sBl[0][0]);

    float cacc[4][4][4];
#pragma unroll
    for (int i = 0; i < 4; i++)
#pragma unroll
        for (int j = 0; j < 4; j++)
#pragma unroll
            for (int r = 0; r < 4; r++) cacc[i][j][r] = 0.f;

    for (int kt = 0; kt < K; kt += 32) {
        // ---- stage A tile (128 x 32 fp32) as hi/lo bf16 ----
#pragma unroll
        for (int i = 0; i < 4; i++) {
            int idx = tid + i * 256;
            int row = idx >> 3;
            int c   = (idx & 7) * 4;
            int grow = bm + row;
            float4 v = make_float4(0.f, 0.f, 0.f, 0.f);
            if (grow < M) v = *(const float4*)(A + (size_t)grow * K + kt + c);
            __nv_bfloat16 h0 = __float2bfloat16(v.x);
            __nv_bfloat16 h1 = __float2bfloat16(v.y);
            __nv_bfloat16 h2 = __float2bfloat16(v.z);
            __nv_bfloat16 h3 = __float2bfloat16(v.w);
            __nv_bfloat16 l0 = __float2bfloat16(v.x - __bfloat162float(h0));
            __nv_bfloat16 l1 = __float2bfloat16(v.y - __bfloat162float(h1));
            __nv_bfloat16 l2 = __float2bfloat16(v.z - __bfloat162float(h2));
            __nv_bfloat16 l3 = __float2bfloat16(v.w - __bfloat162float(h3));
            *(uint2*)&sAh[row][c] = make_uint2(pk(h0, h1), pk(h2, h3));
            *(uint2*)&sAl[row][c] = make_uint2(pk(l0, l1), pk(l2, l3));
        }
        // ---- stage B tile (32 x 128) directly from preconverted bf16 ----
#pragma unroll
        for (int i = 0; i < 2; i++) {
            int idx = tid + i * 256;           // 0..511
            int krow = idx >> 4;               // 0..31
            int c    = (idx & 15) * 8;         // 0..120
            const __nv_bfloat16* ph = Wh + (size_t)(kt + krow) * CC + bn + c;
            const __nv_bfloat16* pl = Wl + (size_t)(kt + krow) * CC + bn + c;
            *(uint4*)&sBh[krow][c] = *(const uint4*)ph;
            *(uint4*)&sBl[krow][c] = *(const uint4*)pl;
        }
        __syncthreads();

#pragma unroll
        for (int half = 0; half < 2; half++) {
            const int kk = half * 16;
            unsigned ah[4][4], al[4][4], bh[4][2], bl[4][2];
#pragma unroll
            for (int mi = 0; mi < 4; mi++) {
                int m = wm * 64 + mi * 16 + a_m_off;
                unsigned off = (unsigned)(m * APITCH + kk + a_k_off) * 2u;
                ldsm_x4(ah[mi][0], ah[mi][1], ah[mi][2], ah[mi][3], sAh0 + off);
                ldsm_x4(al[mi][0], al[mi][1], al[mi][2], al[mi][3], sAl0 + off);
            }
#pragma unroll
            for (int nj = 0; nj < 4; nj++) {
                int n = wn * 32 + nj * 8;
                unsigned off = (unsigned)((kk + b_k_in) * BPITCH + n) * 2u;
                ldsm_x2t(bh[nj][0], bh[nj][1], sBh0 + off);
                ldsm_x2t(bl[nj][0], bl[nj][1], sBl0 + off);
            }
#pragma unroll
            for (int mi = 0; mi < 4; mi++)
#pragma unroll
                for (int nj = 0; nj < 4; nj++) {
                    mma_bf16(cacc[mi][nj], ah[mi], bh[nj]);
                    mma_bf16(cacc[mi][nj], ah[mi], bl[nj]);
                    mma_bf16(cacc[mi][nj], al[mi], bh[nj]);
                }
        }
        __syncthreads();
    }

    const int grp = lane >> 2;
    const int qp  = (lane & 3) * 2;
#pragma unroll
    for (int mi = 0; mi < 4; mi++) {
        int r0 = bm + wm * 64 + mi * 16 + grp;
#pragma unroll
        for (int nj = 0; nj < 4; nj++) {
            int col = bn + wn * 32 + nj * 8 + qp;
            float* base = C + (size_t)r0 * CC + col;
            if (r0 < M)
                *(float2*)base = make_float2(cacc[mi][nj][0], cacc[mi][nj][1]);
            if (r0 + 8 < M)
                *(float2*)(base + 8 * CC) =
                    make_float2(cacc[mi][nj][2], cacc[mi][nj][3]);
        }
    }
}

// ---------------- per-node attention logit projections -----------------------
__global__ void alpha_kernel(const float* __restrict__ aw_s,
                             const float* __restrict__ aw_d) {
    int w = (blockIdx.x * blockDim.x + threadIdx.x) >> 5;
    if (w >= NN) return;
    int lane = threadIdx.x & 31;
    const float4* hr = (const float4*)(g_H + (size_t)w * CC);
    float s = 0.f, d = 0.f;
#pragma unroll
    for (int j = 0; j < 2; j++) {
        float4 h  = hr[lane * 2 + j];
        float4 a  = ((const float4*)aw_s)[lane * 2 + j];
        float4 dd = ((const float4*)aw_d)[lane * 2 + j];
        s += h.x * a.x + h.y * a.y + h.z * a.z + h.w * a.w;
        d += h.x * dd.x + h.y * dd.y + h.z * dd.z + h.w * dd.w;
    }
#pragma unroll
    for (int o = 16; o > 0; o >>= 1) {
        s += __shfl_xor_sync(0xFFFFFFFFu, s, o);
        d += __shfl_xor_sync(0xFFFFFFFFu, d, o);
    }
    if (lane == 0) { g_asrc[w] = s; g_adst[w] = d; }
}

// ---------------- per-dst-node online-softmax aggregation (R6 champion) -----
template <bool ACT, bool GRAPH>
__global__ void aggregate_kernel(const float* __restrict__ bias,
                                 float* __restrict__ out_ext,
                                 const int* __restrict__ batch) {
    int w = (blockIdx.x * blockDim.x + threadIdx.x) >> 5;
    if (w >= NN) return;
    int lane = threadIdx.x & 31;
    int beg = g_off[w], end = g_off[w + 1];
    float ad = g_adst[w];
    float m = -1e30f, s = 0.f;
    float a0 = 0.f, a1 = 0.f, a2 = 0.f, a3 = 0.f;
    float a4 = 0.f, a5 = 0.f, a6 = 0.f, a7 = 0.f;
    const float4* H4 = (const float4*)g_H;
    for (int i = beg; i < end; i++) {
        int src = g_esrc[i];
        float e = g_asrc[src] + ad;
        e = e > 0.f ? e : 0.2f * e;                 // attention leaky relu
        float mn = fmaxf(m, e);
        float sc = __expf(m - mn);
        float p  = __expf(e - mn);
        s = s * sc + p;
        float4 v0 = H4[(size_t)src * 64 + lane * 2];
        float4 v1 = H4[(size_t)src * 64 + lane * 2 + 1];
        a0 = a0 * sc + p * v0.x;  a1 = a1 * sc + p * v0.y;
        a2 = a2 * sc + p * v0.z;  a3 = a3 * sc + p * v0.w;
        a4 = a4 * sc + p * v1.x;  a5 = a5 * sc + p * v1.y;
        a6 = a6 * sc + p * v1.z;  a7 = a7 * sc + p * v1.w;
        m = mn;
    }
    float inv = 1.f / s;
    int c = lane * 8;
    float o[8];
    o[0] = a0 * inv + bias[c + 0];  o[1] = a1 * inv + bias[c + 1];
    o[2] = a2 * inv + bias[c + 2];  o[3] = a3 * inv + bias[c + 3];
    o[4] = a4 * inv + bias[c + 4];  o[5] = a5 * inv + bias[c + 5];
    o[6] = a6 * inv + bias[c + 6];  o[7] = a7 * inv + bias[c + 7];
    if (ACT) {
#pragma unroll
        for (int j = 0; j < 8; j++) o[j] = o[j] > 0.f ? o[j] : 0.01f * o[j];
    }
    float* out = GRAPH ? out_ext : g_X2;
    float* op = out + (size_t)w * CC + c;
    *(float4*)op       = make_float4(o[0], o[1], o[2], o[3]);
    *(float4*)(op + 4) = make_float4(o[4], o[5], o[6], o[7]);
    if (GRAPH) {
        int g = batch[w];
        g = g < 0 ? 0 : (g >= GG ? GG - 1 : g);
        float* gp = g_gout + g * CC + c;
#pragma unroll
        for (int j = 0; j < 8; j++) atomicAdd(gp + j, o[j]);
    }
}

// ---------------- copy graph accumulator into d_out (plain stores) ----------
__global__ void copy_gout_kernel(float* __restrict__ out) {
    int i = blockIdx.x * blockDim.x + threadIdx.x;
    if (i < GG * CC) out[(size_t)NN * CC + i] = g_gout[i];
}

// ---------------- launch -----------------------------------------------------
extern "C" void kernel_launch(void* const* d_in, const int* in_sizes, int n_in,
                              void* d_out, int out_size) {
    const float* x     = (const float*)d_in[0];
    const int*   ei    = (const int*)d_in[1];
    const int*   batch = (const int*)d_in[2];
    const float* W1    = (const float*)d_in[3];
    const float* as1   = (const float*)d_in[4];
    const float* ad1   = (const float*)d_in[5];
    const float* b1    = (const float*)d_in[6];
    const float* W2    = (const float*)d_in[7];
    const float* as2   = (const float*)d_in[8];
    const float* ad2   = (const float*)d_in[9];
    const float* b2    = (const float*)d_in[10];

    float* out = (float*)d_out;

    const int T = 256;
    dim3 ggrid((NN + 127) / 128, CC / 128);
    const int WGRID = (NN * 32 + T - 1) / T;

    // Launch order arranged so mma_gemm lands in the ncu capture slot
    // (skip-5/capture-1 with 2 harness pre-launches -> my 4th launch).
    cvtW_kernel<<<(F1 * CC + CC * CC + T - 1) / T, T>>>(W1, W2);     // 1
    init_kernel<<<(NN + T - 1) / T, T>>>();                          // 2
    count_kernel<<<(EE + T - 1) / T, T>>>(ei);                       // 3
    mma_gemm_kernel<<<ggrid, T>>>(x, 0, 0, NN, F1);                  // 4 <- ncu
    scan_kernel<<<1, 1024>>>();                                      // 5
    fill_kernel<<<(EE + NN + T - 1) / T, T>>>(ei);                   // 6
    alpha_kernel<<<WGRID, T>>>(as1, ad1);                            // 7
    aggregate_kernel<true, false><<<WGRID, T>>>(b1, nullptr, nullptr); // 8

    // Layer 2
    mma_gemm_kernel<<<ggrid, T>>>(nullptr, 1, 1, NN, CC);            // 9
    alpha_kernel<<<WGRID, T>>>(as2, ad2);                            // 10
    aggregate_kernel<false, true><<<WGRID, T>>>(b2, out, batch);     // 11

    copy_gout_kernel<<<(GG * CC + T - 1) / T, T>>>(out);             // 12
}